// round 15
// baseline (speedup 1.0000x reference)
#include <cuda_runtime.h>
#include <cuda_bf16.h>

#define T_DIM 8192

__device__ float        g_scratch = 0.0f;
__device__ unsigned int g_count   = 0u;

__global__ void __launch_bounds__(512, 4)
wl_reduce(const float4* __restrict__ a, const float4* __restrict__ b,
          float* __restrict__ out, int n4, float scale) {
    const int stride = gridDim.x * blockDim.x;
    int i = blockIdx.x * blockDim.x + threadIdx.x;

    float acc0 = 0.0f, acc1 = 0.0f;

    // x2 unroll, strided pair: 4 independent LDG.128 in flight, 32 regs.
    // 512 thr x 4 CTAs/SM = 64 warps/SM, one full wave (grid 592).
    // Converged: kernel 23.9-24.7us at 5.6-5.8 TB/s (measured HBM ceiling
    // for this dual-stream fp32 read); dur 25.06-25.31 across 3 draws.
    // All alternative structures measured slower. Hold.
    for (; i + stride < n4; i += 2 * stride) {
        const int j = i + stride;
        float4 a0 = a[i];
        float4 b0 = b[i];
        float4 a1 = a[j];
        float4 b1 = b[j];

        float w0 = (float)(T_DIM - ((i << 2) & (T_DIM - 1)));
        float w1 = (float)(T_DIM - ((j << 2) & (T_DIM - 1)));

        acc0 = fmaf(fabsf(a0.x - b0.x), w0,        acc0);
        acc0 = fmaf(fabsf(a0.y - b0.y), w0 - 1.0f, acc0);
        acc0 = fmaf(fabsf(a0.z - b0.z), w0 - 2.0f, acc0);
        acc0 = fmaf(fabsf(a0.w - b0.w), w0 - 3.0f, acc0);

        acc1 = fmaf(fabsf(a1.x - b1.x), w1,        acc1);
        acc1 = fmaf(fabsf(a1.y - b1.y), w1 - 1.0f, acc1);
        acc1 = fmaf(fabsf(a1.z - b1.z), w1 - 2.0f, acc1);
        acc1 = fmaf(fabsf(a1.w - b1.w), w1 - 3.0f, acc1);
    }
    if (i < n4) {
        float4 va = a[i];
        float4 vb = b[i];
        float w = (float)(T_DIM - ((i << 2) & (T_DIM - 1)));
        acc0 = fmaf(fabsf(va.x - vb.x), w,        acc0);
        acc0 = fmaf(fabsf(va.y - vb.y), w - 1.0f, acc0);
        acc0 = fmaf(fabsf(va.z - vb.z), w - 2.0f, acc0);
        acc0 = fmaf(fabsf(va.w - vb.w), w - 3.0f, acc0);
    }

    float acc = acc0 + acc1;

    #pragma unroll
    for (int o = 16; o > 0; o >>= 1)
        acc += __shfl_down_sync(0xffffffffu, acc, o);

    __shared__ float smem[16];
    const int lane = threadIdx.x & 31;
    const int wid  = threadIdx.x >> 5;
    if (lane == 0) smem[wid] = acc;
    __syncthreads();
    if (wid == 0) {
        acc = (lane < 16) ? smem[lane] : 0.0f;
        #pragma unroll
        for (int o = 8; o > 0; o >>= 1)
            acc += __shfl_down_sync(0xffffffffu, acc, o);

        if (lane == 0) {
            atomicAdd(&g_scratch, acc);
            __threadfence();
            unsigned int old = atomicAdd(&g_count, 1u);
            if (old == gridDim.x - 1) {
                out[0]    = g_scratch * scale;
                g_scratch = 0.0f;
                g_count   = 0u;
            }
        }
    }
}

extern "C" void kernel_launch(void* const* d_in, const int* in_sizes, int n_in,
                              void* d_out, int out_size) {
    const float4* y_pred = (const float4*)d_in[0];
    const float4* y_true = (const float4*)d_in[1];
    float* out = (float*)d_out;

    const int n  = in_sizes[0];   // 32*64*8192
    const int n4 = n / 4;

    const double T = (double)T_DIM;
    const double C = 64.0;
    const double B = (double)n / (T * C);
    const float scale = (float)(2.0 / (T * C * (T + 1.0) * B));

    // One full resident wave: 148 SMs x 4 CTAs x 512 thr = 64 warps/SM.
    const int threads = 512;
    int blocks = 148 * 4;
    int max_blocks = (n4 + threads - 1) / threads;
    if (blocks > max_blocks) blocks = max_blocks;

    wl_reduce<<<blocks, threads>>>(y_pred, y_true, out, n4, scale);
}

// round 16
// speedup vs baseline: 1.0166x; 1.0166x over previous
#include <cuda_runtime.h>
#include <cuda_bf16.h>

#define T_DIM 8192

__device__ float        g_scratch = 0.0f;
__device__ unsigned int g_count   = 0u;

__global__ void __launch_bounds__(512, 4)
wl_reduce(const float4* __restrict__ a, const float4* __restrict__ b,
          float* __restrict__ out, int n4, float scale) {
    const int stride = gridDim.x * blockDim.x;
    int i = blockIdx.x * blockDim.x + threadIdx.x;

    float acc0 = 0.0f, acc1 = 0.0f;

    // x2 unroll, strided pair: 4 independent LDG.128 in flight, 32 regs.
    // 512 thr x 4 CTAs/SM = 64 warps/SM, one full wave (grid 592).
    // Converged config at the measured HBM ceiling (23.8-24.7us kernel,
    // 5.6-5.8 TB/s) over 6 profiled draws. Every alternative structure
    // measured slower; variance dominates all residual tunables. Hold.
    for (; i + stride < n4; i += 2 * stride) {
        const int j = i + stride;
        float4 a0 = a[i];
        float4 b0 = b[i];
        float4 a1 = a[j];
        float4 b1 = b[j];

        float w0 = (float)(T_DIM - ((i << 2) & (T_DIM - 1)));
        float w1 = (float)(T_DIM - ((j << 2) & (T_DIM - 1)));

        acc0 = fmaf(fabsf(a0.x - b0.x), w0,        acc0);
        acc0 = fmaf(fabsf(a0.y - b0.y), w0 - 1.0f, acc0);
        acc0 = fmaf(fabsf(a0.z - b0.z), w0 - 2.0f, acc0);
        acc0 = fmaf(fabsf(a0.w - b0.w), w0 - 3.0f, acc0);

        acc1 = fmaf(fabsf(a1.x - b1.x), w1,        acc1);
        acc1 = fmaf(fabsf(a1.y - b1.y), w1 - 1.0f, acc1);
        acc1 = fmaf(fabsf(a1.z - b1.z), w1 - 2.0f, acc1);
        acc1 = fmaf(fabsf(a1.w - b1.w), w1 - 3.0f, acc1);
    }
    if (i < n4) {
        float4 va = a[i];
        float4 vb = b[i];
        float w = (float)(T_DIM - ((i << 2) & (T_DIM - 1)));
        acc0 = fmaf(fabsf(va.x - vb.x), w,        acc0);
        acc0 = fmaf(fabsf(va.y - vb.y), w - 1.0f, acc0);
        acc0 = fmaf(fabsf(va.z - vb.z), w - 2.0f, acc0);
        acc0 = fmaf(fabsf(va.w - vb.w), w - 3.0f, acc0);
    }

    float acc = acc0 + acc1;

    #pragma unroll
    for (int o = 16; o > 0; o >>= 1)
        acc += __shfl_down_sync(0xffffffffu, acc, o);

    __shared__ float smem[16];
    const int lane = threadIdx.x & 31;
    const int wid  = threadIdx.x >> 5;
    if (lane == 0) smem[wid] = acc;
    __syncthreads();
    if (wid == 0) {
        acc = (lane < 16) ? smem[lane] : 0.0f;
        #pragma unroll
        for (int o = 8; o > 0; o >>= 1)
            acc += __shfl_down_sync(0xffffffffu, acc, o);

        if (lane == 0) {
            atomicAdd(&g_scratch, acc);
            __threadfence();
            unsigned int old = atomicAdd(&g_count, 1u);
            if (old == gridDim.x - 1) {
                out[0]    = g_scratch * scale;
                g_scratch = 0.0f;
                g_count   = 0u;
            }
        }
    }
}

extern "C" void kernel_launch(void* const* d_in, const int* in_sizes, int n_in,
                              void* d_out, int out_size) {
    const float4* y_pred = (const float4*)d_in[0];
    const float4* y_true = (const float4*)d_in[1];
    float* out = (float*)d_out;

    const int n  = in_sizes[0];   // 32*64*8192
    const int n4 = n / 4;

    const double T = (double)T_DIM;
    const double C = 64.0;
    const double B = (double)n / (T * C);
    const float scale = (float)(2.0 / (T * C * (T + 1.0) * B));

    // One full resident wave: 148 SMs x 4 CTAs x 512 thr = 64 warps/SM.
    const int threads = 512;
    int blocks = 148 * 4;
    int max_blocks = (n4 + threads - 1) / threads;
    if (blocks > max_blocks) blocks = max_blocks;

    wl_reduce<<<blocks, threads>>>(y_pred, y_true, out, n4, scale);
}